// round 2
// baseline (speedup 1.0000x reference)
#include <cuda_runtime.h>
#include <cstdint>

#define B 32
#define F 1024
#define S 2048
#define KK 16
#define NSPLIT 8
#define RPS (S / NSPLIT)   // 256 rows per split

// Scratch (allocation-free rule: __device__ globals)
__device__ float g_partial[B * NSPLIT * S];   // 2 MB partial column sums
__device__ int   g_idx[B * KK];               // top-k indices per batch

// ---------------------------------------------------------------------------
// Kernel 1: partial column sums of w[B, S, S] over a 256-row slice.
// float4 loads: warp reads 512 contiguous bytes per iteration (perfect
// coalescing), unroll 8 for MLP. 1024 blocks x 128 threads.
// ---------------------------------------------------------------------------
__global__ void colsum_partial_kernel(const float* __restrict__ w) {
    const int c4    = blockIdx.x * blockDim.x + threadIdx.x;  // float4 col group
    const int split = blockIdx.y;
    const int b     = blockIdx.z;

    const float4* wp = reinterpret_cast<const float4*>(w + (size_t)b * S * S);
    const float4* p  = wp + (size_t)(split * RPS) * (S / 4) + c4;

    float4 acc = make_float4(0.f, 0.f, 0.f, 0.f);
#pragma unroll 8
    for (int r = 0; r < RPS; ++r) {
        float4 v = __ldg(p);
        acc.x += v.x; acc.y += v.y; acc.z += v.z; acc.w += v.w;
        p += S / 4;
    }

    float4* outp = reinterpret_cast<float4*>(g_partial)
                 + (size_t)(b * NSPLIT + split) * (S / 4) + c4;
    *outp = acc;
}

// ---------------------------------------------------------------------------
// Kernel 2: per-batch fold of 8 partials + 16-round packed argmax top-k.
// Key = (monotone float bits << 32) | (S-1-col)  ->  max key = largest value,
// ties broken toward the LOWEST column index (matches lax.top_k).
// One block per batch, 512 threads.
// ---------------------------------------------------------------------------
__global__ void reduce_topk_kernel() {
    __shared__ unsigned long long skey[S];
    __shared__ unsigned long long red[512];

    const int b = blockIdx.x;
    const int t = threadIdx.x;

    for (int c = t; c < S; c += 512) {
        float s = 0.f;
#pragma unroll
        for (int p = 0; p < NSPLIT; ++p)
            s += g_partial[(size_t)(b * NSPLIT + p) * S + c];
        unsigned int bits = __float_as_uint(s);
        // monotone order-preserving map (handles negatives too)
        bits = (bits & 0x80000000u) ? ~bits : (bits | 0x80000000u);
        skey[c] = ((unsigned long long)bits << 32)
                | (unsigned int)(S - 1 - c);
    }
    __syncthreads();

    for (int k = 0; k < KK; ++k) {
        unsigned long long best = 0ull;
        for (int c = t; c < S; c += 512) {
            unsigned long long v = skey[c];
            best = (v > best) ? v : best;
        }
        red[t] = best;
        __syncthreads();
#pragma unroll
        for (int off = 256; off > 0; off >>= 1) {
            if (t < off) {
                unsigned long long v = red[t + off];
                if (v > red[t]) red[t] = v;
            }
            __syncthreads();
        }
        const unsigned long long win = red[0];
        const int col = S - 1 - (int)(win & 0xFFFFFFFFu);
        if (t == 0) {
            g_idx[b * KK + k] = col;
            skey[col] = 0ull;   // mask the winner
        }
        __syncthreads();
    }
}

// ---------------------------------------------------------------------------
// Kernel 3: gather out[b,f,k] = x[b,f,idx[b,k]]. Coalesced writes; the 16
// scattered 4B reads per (b,f) row are L2-friendly (16 MB total traffic).
// ---------------------------------------------------------------------------
__global__ void gather_kernel(const float* __restrict__ x,
                              float* __restrict__ out) {
    const int i = blockIdx.x * blockDim.x + threadIdx.x;
    if (i >= B * F * KK) return;
    const int k = i % KK;
    const int f = (i / KK) % F;
    const int b = i / (KK * F);
    const int col = g_idx[b * KK + k];
    out[i] = __ldg(x + (size_t)b * F * S + (size_t)f * S + col);
}

// ---------------------------------------------------------------------------
extern "C" void kernel_launch(void* const* d_in, const int* in_sizes, int n_in,
                              void* d_out, int out_size) {
    const float* x = (const float*)d_in[0];  // [B, F, S]
    const float* w = (const float*)d_in[1];  // [B, S, S]
    float* out = (float*)d_out;              // [B, F, K]

    dim3 g1(S / (128 * 4), NSPLIT, B);       // (4, 8, 32)
    colsum_partial_kernel<<<g1, 128>>>(w);

    reduce_topk_kernel<<<B, 512>>>();

    const int total = B * F * KK;
    gather_kernel<<<(total + 255) / 256, 256>>>(x, out);
}